// round 1
// baseline (speedup 1.0000x reference)
#include <cuda_runtime.h>
#include <math.h>

// ---------------------------------------------------------------------------
// Scratch buffers (__device__ globals — allocation-free per harness rules)
// ---------------------------------------------------------------------------
__device__ float g_s0[128 * 128 * 256];            // conv2d block0 out
__device__ float g_s1[256 * 64 * 128];             // conv2d block1 out
__device__ float g_p0[128 * 12 * 128 * 256];       // conv3d block0 out (201MB)
__device__ float g_p1[256 * 6 * 64 * 128];         // conv3d block1 out
__device__ float g_feats[512 * 4 * 32 * 64];       // concat(p2, s2)
__device__ float g_yn[512 * 8192];                 // layernorm out (channel-major)
__device__ float g_qkv[8192 * 1536];               // qkv (token-major)
__device__ float g_at[8192 * 512];                 // attention out (token-major)

// ---------------------------------------------------------------------------
// Helpers
// ---------------------------------------------------------------------------
__device__ __forceinline__ float gelu_tanh(float x) {
    float x3 = x * x * x;
    float t = tanhf(0.7978845608028654f * (x + 0.044715f * x3));
    return 0.5f * x * (1.0f + t);
}

#define MMA16()                                                                    \
    _Pragma("unroll")                                                              \
    for (int kq = 0; kq < 16; kq++) {                                              \
        float4 a = *reinterpret_cast<const float4*>(&As[kq][ty * 4]);              \
        float4 b = *reinterpret_cast<const float4*>(&Bs[kq][tx * 4]);              \
        acc[0][0] = fmaf(a.x, b.x, acc[0][0]); acc[0][1] = fmaf(a.x, b.y, acc[0][1]); \
        acc[0][2] = fmaf(a.x, b.z, acc[0][2]); acc[0][3] = fmaf(a.x, b.w, acc[0][3]); \
        acc[1][0] = fmaf(a.y, b.x, acc[1][0]); acc[1][1] = fmaf(a.y, b.y, acc[1][1]); \
        acc[1][2] = fmaf(a.y, b.z, acc[1][2]); acc[1][3] = fmaf(a.y, b.w, acc[1][3]); \
        acc[2][0] = fmaf(a.z, b.x, acc[2][0]); acc[2][1] = fmaf(a.z, b.y, acc[2][1]); \
        acc[2][2] = fmaf(a.z, b.z, acc[2][2]); acc[2][3] = fmaf(a.z, b.w, acc[2][3]); \
        acc[3][0] = fmaf(a.w, b.x, acc[3][0]); acc[3][1] = fmaf(a.w, b.y, acc[3][1]); \
        acc[3][2] = fmaf(a.w, b.z, acc[3][2]); acc[3][3] = fmaf(a.w, b.w, acc[3][3]); \
    }

// ---------------------------------------------------------------------------
// Implicit-GEMM convolution (stride/pad/kernel generic), fused bias (+GELU).
// Y[m, n] = sum_k W[m, k] * im2col(X)[k, n]; output channel-major.
// M = Cout (mult of 64), N = Nvox (mult of 64); K arbitrary (guarded).
// ---------------------------------------------------------------------------
struct ConvParams {
    const float* x; const float* w; const float* bias; float* out;
    int Cin, D, H, W;
    int Dout, Hout, Wout;
    int KD, KH, KW;
    int sd, sh, sw, pd, ph, pw;
    int K, Nvox;
    int outStrideC, outOffset;
    int gelu;
};

__global__ __launch_bounds__(256) void conv_gemm_kernel(ConvParams p) {
    __shared__ __align__(16) float As[16][64];
    __shared__ __align__(16) float Bs[16][64];

    const int tid = threadIdx.x;
    const int bn = blockIdx.x, bm = blockIdx.y;
    const int tx = tid & 15, ty = tid >> 4;
    const int ln = tid & 63, kgrp = tid >> 6;        // B-load mapping
    const int lm = tid >> 2, lk4 = (tid & 3) << 2;   // A-load mapping

    const int HWo = p.Hout * p.Wout;
    const int n = bn * 64 + ln;
    const int od = n / HWo; int rr = n - od * HWo;
    const int oh = rr / p.Wout; const int ow = rr - oh * p.Wout;
    const int id0 = od * p.sd - p.pd;
    const int ih0 = oh * p.sh - p.ph;
    const int iw0 = ow * p.sw - p.pw;
    const int KHW = p.KH * p.KW;
    const int KV = p.KD * KHW;
    const int m_base = bm * 64;

    float acc[4][4];
#pragma unroll
    for (int i = 0; i < 4; i++)
#pragma unroll
        for (int j = 0; j < 4; j++) acc[i][j] = 0.f;

    for (int kt = 0; kt < p.K; kt += 16) {
        // A tile: weights [64 m][16 k]
#pragma unroll
        for (int i = 0; i < 4; i++) {
            int k = kt + lk4 + i;
            As[lk4 + i][lm] = (k < p.K) ? p.w[(size_t)(m_base + lm) * p.K + k] : 0.f;
        }
        // B tile: gathered input [16 k][64 n]
#pragma unroll
        for (int r4 = 0; r4 < 4; r4++) {
            int kk = kgrp * 4 + r4;
            int k = kt + kk;
            float v = 0.f;
            if (k < p.K) {
                int ci = k / KV; int tap = k - ci * KV;
                int kd = tap / KHW; int t2 = tap - kd * KHW;
                int kh = t2 / p.KW; int kw = t2 - kh * p.KW;
                int id = id0 + kd, ih = ih0 + kh, iw = iw0 + kw;
                if ((unsigned)id < (unsigned)p.D && (unsigned)ih < (unsigned)p.H &&
                    (unsigned)iw < (unsigned)p.W)
                    v = p.x[(size_t)((ci * p.D + id) * p.H + ih) * p.W + iw];
            }
            Bs[kk][ln] = v;
        }
        __syncthreads();
        MMA16();
        __syncthreads();
    }

#pragma unroll
    for (int i = 0; i < 4; i++) {
        int m = m_base + ty * 4 + i;
        float bv = p.bias[m];
        float4 o;
        o.x = acc[i][0] + bv; o.y = acc[i][1] + bv;
        o.z = acc[i][2] + bv; o.w = acc[i][3] + bv;
        if (p.gelu) {
            o.x = gelu_tanh(o.x); o.y = gelu_tanh(o.y);
            o.z = gelu_tanh(o.z); o.w = gelu_tanh(o.w);
        }
        *reinterpret_cast<float4*>(p.out + (size_t)m * p.outStrideC + p.outOffset +
                                   bn * 64 + tx * 4) = o;
    }
}

// ---------------------------------------------------------------------------
// Token GEMM: C[t, j] = sum_k A[k][t] * B[k, j] + bias[j]
//   ALAYOUT 0: A is k-major [K x T];  ALAYOUT 1: A is t-major [T x K]
//   OUTMODE 0: C token-major [T x J] = v
//   OUTMODE 1: C channel-major [J x T] += v   (residual add)
// T, J multiples of 64; K multiple of 16.
// ---------------------------------------------------------------------------
template <int ALAYOUT, int OUTMODE>
__global__ __launch_bounds__(256) void tok_gemm_kernel(
    const float* __restrict__ A, const float* __restrict__ B,
    const float* __restrict__ bias, float* __restrict__ C,
    int T, int J, int K) {
    __shared__ __align__(16) float As[16][64];
    __shared__ __align__(16) float Bs[16][64];

    const int tid = threadIdx.x;
    const int bj = blockIdx.x, bt = blockIdx.y;
    const int tx = tid & 15, ty = tid >> 4;
    const int lj = tid & 63, kgrp = tid >> 6;

    float acc[4][4];
#pragma unroll
    for (int i = 0; i < 4; i++)
#pragma unroll
        for (int j = 0; j < 4; j++) acc[i][j] = 0.f;

    for (int kt = 0; kt < K; kt += 16) {
        if (ALAYOUT == 0) {
            const int lt = tid & 63;
#pragma unroll
            for (int r4 = 0; r4 < 4; r4++) {
                int kk = kgrp * 4 + r4;
                As[kk][lt] = A[(size_t)(kt + kk) * T + bt * 64 + lt];
            }
        } else {
            const int lt = tid >> 2, lk4 = (tid & 3) << 2;
            float4 v = *reinterpret_cast<const float4*>(
                A + (size_t)(bt * 64 + lt) * K + kt + lk4);
            As[lk4 + 0][lt] = v.x; As[lk4 + 1][lt] = v.y;
            As[lk4 + 2][lt] = v.z; As[lk4 + 3][lt] = v.w;
        }
#pragma unroll
        for (int r4 = 0; r4 < 4; r4++) {
            int kk = kgrp * 4 + r4;
            Bs[kk][lj] = B[(size_t)(kt + kk) * J + bj * 64 + lj];
        }
        __syncthreads();
        MMA16();
        __syncthreads();
    }

    if (OUTMODE == 0) {
#pragma unroll
        for (int i = 0; i < 4; i++) {
            int t = bt * 64 + ty * 4 + i;
            int j0 = bj * 64 + tx * 4;
            float4 o;
            o.x = acc[i][0] + bias[j0 + 0];
            o.y = acc[i][1] + bias[j0 + 1];
            o.z = acc[i][2] + bias[j0 + 2];
            o.w = acc[i][3] + bias[j0 + 3];
            *reinterpret_cast<float4*>(C + (size_t)t * J + j0) = o;
        }
    } else {
#pragma unroll
        for (int j = 0; j < 4; j++) {
            int jj = bj * 64 + tx * 4 + j;
            float bv = bias[jj];
            int t0 = bt * 64 + ty * 4;
            float4* cp = reinterpret_cast<float4*>(C + (size_t)jj * T + t0);
            float4 o = *cp;
            o.x += acc[0][j] + bv; o.y += acc[1][j] + bv;
            o.z += acc[2][j] + bv; o.w += acc[3][j] + bv;
            *cp = o;
        }
    }
}

// ---------------------------------------------------------------------------
// LayerNorm over C=512, channel-major in/out. Block = (32 tokens, 8 ch-groups).
// ---------------------------------------------------------------------------
__global__ __launch_bounds__(256) void layernorm_kernel(
    const float* __restrict__ x, const float* __restrict__ g,
    const float* __restrict__ b, float* __restrict__ y, int T) {
    const int tx = threadIdx.x;      // token lane (32)
    const int ty = threadIdx.y;      // channel group (8)
    const int t = blockIdx.x * 32 + tx;

    float s = 0.f, ss = 0.f;
#pragma unroll
    for (int i = 0; i < 64; i++) {
        int c = ty * 64 + i;
        float v = x[(size_t)c * T + t];
        s += v; ss += v * v;
    }
    __shared__ float shs[8][32], shss[8][32];
    __shared__ float smu[32], srs[32];
    shs[ty][tx] = s; shss[ty][tx] = ss;
    __syncthreads();
    if (ty == 0) {
        float S = 0.f, SS = 0.f;
#pragma unroll
        for (int j = 0; j < 8; j++) { S += shs[j][tx]; SS += shss[j][tx]; }
        float mu = S * (1.f / 512.f);
        float var = SS * (1.f / 512.f) - mu * mu;
        smu[tx] = mu;
        srs[tx] = rsqrtf(var + 1e-5f);
    }
    __syncthreads();
    float mu = smu[tx], rs = srs[tx];
#pragma unroll
    for (int i = 0; i < 64; i++) {
        int c = ty * 64 + i;
        float v = x[(size_t)c * T + t];
        y[(size_t)c * T + t] = (v - mu) * rs * g[c] + b[c];
    }
}

// ---------------------------------------------------------------------------
// 3D Neighborhood attention: window (5,7,7) = 245 offsets, zero-pad masking.
// One warp per (token, head). Grid: (T/8, NHEADS); block 256 (8 warps).
// qkv token-major [T x 1536], layout [3][head][64]. Output at[t*512 + h*64 + e].
// ---------------------------------------------------------------------------
__global__ __launch_bounds__(256) void natt_kernel(
    const float* __restrict__ qkv, float* __restrict__ at) {
    const int warp = threadIdx.x >> 5;
    const int lane = threadIdx.x & 31;
    const int t = blockIdx.x * 8 + warp;
    const int head = blockIdx.y;
    const int d = t >> 11;            // / (32*64)
    const int hh = (t >> 6) & 31;
    const int ww = t & 63;

    __shared__ float qsh[8][64];
    const float* qp = qkv + (size_t)t * 1536 + head * 64;
    qsh[warp][lane] = qp[lane] * 0.125f;          // hd^-0.5 = 64^-0.5
    qsh[warp][lane + 32] = qp[lane + 32] * 0.125f;
    __syncwarp();

    float sc[8];
    float m = -1e30f;
#pragma unroll
    for (int it = 0; it < 8; it++) {
        int nb = it * 32 + lane;
        float dot = -1e30f;
        if (nb < 245) {
            int od = nb / 49; int r = nb - od * 49;
            int oh = r / 7;   int ow = r - oh * 7;
            int nd = d + od - 2, nh = hh + oh - 3, nw = ww + ow - 3;
            if ((unsigned)nd < 4u && (unsigned)nh < 32u && (unsigned)nw < 64u) {
                int nt = (nd * 32 + nh) * 64 + nw;
                const float4* kp = reinterpret_cast<const float4*>(
                    qkv + (size_t)nt * 1536 + 512 + head * 64);
                float s = 0.f;
#pragma unroll
                for (int q4 = 0; q4 < 16; q4++) {
                    float4 kv = kp[q4];
                    s = fmaf(qsh[warp][q4 * 4 + 0], kv.x, s);
                    s = fmaf(qsh[warp][q4 * 4 + 1], kv.y, s);
                    s = fmaf(qsh[warp][q4 * 4 + 2], kv.z, s);
                    s = fmaf(qsh[warp][q4 * 4 + 3], kv.w, s);
                }
                dot = s;
            }
        }
        sc[it] = dot;
        m = fmaxf(m, dot);
    }
#pragma unroll
    for (int o = 16; o; o >>= 1) m = fmaxf(m, __shfl_xor_sync(0xffffffffu, m, o));

    float l = 0.f;
#pragma unroll
    for (int it = 0; it < 8; it++) {
        float e = (sc[it] > -1e29f) ? __expf(sc[it] - m) : 0.f;
        sc[it] = e;
        l += e;
    }
#pragma unroll
    for (int o = 16; o; o >>= 1) l += __shfl_xor_sync(0xffffffffu, l, o);

    float acc0 = 0.f, acc1 = 0.f;
#pragma unroll
    for (int it = 0; it < 8; it++) {
        for (int j = 0; j < 32; j++) {
            int nb = it * 32 + j;
            if (nb < 245) {
                float pb = __shfl_sync(0xffffffffu, sc[it], j);
                if (pb > 0.f) {
                    int od = nb / 49; int r = nb - od * 49;
                    int oh = r / 7;   int ow = r - oh * 7;
                    int nd = d + od - 2, nh = hh + oh - 3, nw = ww + ow - 3;
                    int nt = (nd * 32 + nh) * 64 + nw;
                    const float* vp = qkv + (size_t)nt * 1536 + 1024 + head * 64;
                    acc0 = fmaf(pb, vp[lane], acc0);
                    acc1 = fmaf(pb, vp[lane + 32], acc1);
                }
            }
        }
    }
    float inv = 1.f / l;
    float* op = at + (size_t)t * 512 + head * 64;
    op[lane] = acc0 * inv;
    op[lane + 32] = acc1 * inv;
}

// ---------------------------------------------------------------------------
// Host launcher
// ---------------------------------------------------------------------------
extern "C" void kernel_launch(void* const* d_in, const int* in_sizes, int n_in,
                              void* d_out, int out_size) {
    const float* x2d  = (const float*)d_in[0];
    const float* x3d  = (const float*)d_in[1];
    const float* sw0  = (const float*)d_in[2];  const float* sb0 = (const float*)d_in[3];
    const float* sw1  = (const float*)d_in[4];  const float* sb1 = (const float*)d_in[5];
    const float* sw2  = (const float*)d_in[6];  const float* sb2 = (const float*)d_in[7];
    const float* pw0  = (const float*)d_in[8];  const float* pb0 = (const float*)d_in[9];
    const float* pw1  = (const float*)d_in[10]; const float* pb1 = (const float*)d_in[11];
    const float* pw2  = (const float*)d_in[12]; const float* pb2 = (const float*)d_in[13];
    const float* latw = (const float*)d_in[14]; const float* latb = (const float*)d_in[15];
    const float* lng  = (const float*)d_in[16]; const float* lnb  = (const float*)d_in[17];
    const float* qkvw = (const float*)d_in[18]; const float* qkvb = (const float*)d_in[19];
    const float* pjw  = (const float*)d_in[20]; const float* pjb  = (const float*)d_in[21];
    float* lat = (float*)d_out;

    float *s0, *s1, *p0, *p1, *feats, *yn, *qkvB, *at;
    cudaGetSymbolAddress((void**)&s0, g_s0);
    cudaGetSymbolAddress((void**)&s1, g_s1);
    cudaGetSymbolAddress((void**)&p0, g_p0);
    cudaGetSymbolAddress((void**)&p1, g_p1);
    cudaGetSymbolAddress((void**)&feats, g_feats);
    cudaGetSymbolAddress((void**)&yn, g_yn);
    cudaGetSymbolAddress((void**)&qkvB, g_qkv);
    cudaGetSymbolAddress((void**)&at, g_at);

    // ---- 2D conv tower (as 3D with D=1, KD=1) ----
    {
        ConvParams p{ x2d, sw0, sb0, s0,
                      8, 1, 256, 512,   1, 128, 256,   1, 3, 3,
                      1, 2, 2, 0, 1, 1,  72, 32768, 32768, 0, 1 };
        conv_gemm_kernel<<<dim3(32768 / 64, 128 / 64), 256>>>(p);
    }
    {
        ConvParams p{ s0, sw1, sb1, s1,
                      128, 1, 128, 256,  1, 64, 128,   1, 3, 3,
                      1, 2, 2, 0, 1, 1,  1152, 8192, 8192, 0, 1 };
        conv_gemm_kernel<<<dim3(8192 / 64, 256 / 64), 256>>>(p);
    }
    {   // writes directly into feats slot d=3
        ConvParams p{ s1, sw2, sb2, feats,
                      256, 1, 64, 128,   1, 32, 64,    1, 3, 3,
                      1, 2, 2, 0, 1, 1,  2304, 2048, 8192, 3 * 2048, 1 };
        conv_gemm_kernel<<<dim3(2048 / 64, 512 / 64), 256>>>(p);
    }

    // ---- 3D conv tower ----
    {
        ConvParams p{ x3d, pw0, pb0, p0,
                      5, 24, 256, 512,   12, 128, 256,  3, 3, 3,
                      2, 2, 2, 1, 1, 1,  135, 393216, 393216, 0, 1 };
        conv_gemm_kernel<<<dim3(393216 / 64, 128 / 64), 256>>>(p);
    }
    {
        ConvParams p{ p0, pw1, pb1, p1,
                      128, 12, 128, 256, 6, 64, 128,    3, 3, 3,
                      2, 2, 2, 1, 1, 1,  3456, 49152, 49152, 0, 1 };
        conv_gemm_kernel<<<dim3(49152 / 64, 256 / 64), 256>>>(p);
    }
    {   // writes into feats slots d=0..2
        ConvParams p{ p1, pw2, pb2, feats,
                      256, 6, 64, 128,   3, 32, 64,     3, 3, 3,
                      2, 2, 2, 1, 1, 1,  6912, 6144, 8192, 0, 1 };
        conv_gemm_kernel<<<dim3(6144 / 64, 512 / 64), 256>>>(p);
    }

    // ---- lateral 1x1x1 conv (512->512), no gelu, output -> d_out (lat) ----
    {
        ConvParams p{ feats, latw, latb, lat,
                      512, 4, 32, 64,    4, 32, 64,     1, 1, 1,
                      1, 1, 1, 0, 0, 0,  512, 8192, 8192, 0, 0 };
        conv_gemm_kernel<<<dim3(8192 / 64, 512 / 64), 256>>>(p);
    }

    // ---- 3 neighborhood-attention blocks (in place on lat) ----
    for (int i = 0; i < 3; i++) {
        layernorm_kernel<<<8192 / 32, dim3(32, 8)>>>(lat, lng + i * 512, lnb + i * 512,
                                                     yn, 8192);
        tok_gemm_kernel<0, 0><<<dim3(1536 / 64, 8192 / 64), 256>>>(
            yn, qkvw + (size_t)i * 512 * 1536, qkvb + i * 1536, qkvB, 8192, 1536, 512);
        natt_kernel<<<dim3(8192 / 8, 8), 256>>>(qkvB, at);
        tok_gemm_kernel<1, 1><<<dim3(512 / 64, 8192 / 64), 256>>>(
            at, pjw + (size_t)i * 512 * 512, pjb + i * 512, lat, 8192, 512, 512);
    }
}

// round 2
// speedup vs baseline: 1.5204x; 1.5204x over previous
#include <cuda_runtime.h>
#include <math.h>

// ---------------------------------------------------------------------------
// Scratch buffers
// ---------------------------------------------------------------------------
__device__ float g_s0[128 * 128 * 256];
__device__ float g_s1[256 * 64 * 128];
__device__ float g_p0[128 * 12 * 128 * 256];
__device__ float g_p1[256 * 6 * 64 * 128];
__device__ float g_feats[512 * 4 * 32 * 64];
__device__ float g_yn[512 * 8192];
__device__ float g_qkv[8192 * 1536];
__device__ float g_at[8192 * 512];
__device__ int2  g_dec[8192];          // conv k-decode table
__device__ int   g_ndelta[256];        // natt neighbor token delta
__device__ int   g_npack[256];         // natt packed (od,oh,ow)

__device__ __forceinline__ float gelu_tanh(float x) {
    float x3 = x * x * x;
    float t = tanhf(0.7978845608028654f * (x + 0.044715f * x3));
    return 0.5f * x * (1.0f + t);
}

// ---------------------------------------------------------------------------
// Decode-table init kernels (cheap, launched per conv / once for natt)
// ---------------------------------------------------------------------------
__global__ void conv_decode_kernel(int K, int Kpad, int KV, int KHW, int KW,
                                   int D, int H, int W) {
    int k = blockIdx.x * 256 + threadIdx.x;
    if (k >= Kpad) return;
    if (k < K) {
        int ci = k / KV; int tap = k - ci * KV;
        int kd = tap / KHW; int t2 = tap - kd * KHW;
        int kh = t2 / KW; int kw = t2 - kh * KW;
        g_dec[k] = make_int2(((ci * D + kd) * H + kh) * W + kw,
                             (kd << 20) | (kh << 10) | kw);
    } else {
        g_dec[k] = make_int2(0, 1023 << 20);   // kd=1023 -> always out of bounds
    }
}

__global__ void natt_table_kernel() {
    int nb = threadIdx.x;
    if (nb < 245) {
        int od = nb / 49; int r = nb - od * 49;
        int oh = r / 7;   int ow = r - oh * 7;
        g_ndelta[nb] = (od - 2) * 2048 + (oh - 3) * 64 + (ow - 3);
        g_npack[nb]  = (od << 16) | (oh << 8) | ow;
    }
}

// ---------------------------------------------------------------------------
// Implicit-GEMM conv, 64(M) x 128(N) tile, k-tile 16, decode-table gather.
// ---------------------------------------------------------------------------
struct ConvParams {
    const float* x; const float* w; const float* bias; float* out;
    int D, H, W;
    int Hout, Wout;
    int sd, sh, sw, pd, ph, pw;
    int K, Kpad;
    int outStrideC, outOffset;
    int gelu;
};

__global__ __launch_bounds__(256) void conv_gemm_kernel(ConvParams p) {
    __shared__ __align__(16) float As[16][64];
    __shared__ __align__(16) float Bs[16][128];

    const int tid = threadIdx.x;
    const int bn = blockIdx.x, bm = blockIdx.y;
    const int tx = tid & 15, ty = tid >> 4;
    const int ln = tid & 127, kgrp = tid >> 7;
    const int lm = tid >> 2, lk = tid & 3;

    const int HWo = p.Hout * p.Wout;
    const int n = bn * 128 + ln;
    const int od = n / HWo; int rr = n - od * HWo;
    const int oh = rr / p.Wout; const int ow = rr - oh * p.Wout;
    const int id0 = od * p.sd - p.pd;
    const int ih0 = oh * p.sh - p.ph;
    const int iw0 = ow * p.sw - p.pw;
    const int base = (id0 * p.H + ih0) * p.W + iw0;
    const int m_base = bm * 64;
    const float* wrow = p.w + (size_t)(m_base + lm) * p.K;

    float acc[4][8];
#pragma unroll
    for (int i = 0; i < 4; i++)
#pragma unroll
        for (int j = 0; j < 8; j++) acc[i][j] = 0.f;

    for (int kt = 0; kt < p.Kpad; kt += 16) {
        // A tile (weights): 4 guarded scalars per thread
#pragma unroll
        for (int i = 0; i < 4; i++) {
            int k = kt + lk + i * 4;
            As[lk + i * 4][lm] = (k < p.K) ? wrow[k] : 0.f;
        }
        // B tile (gathered input): 8 per thread via decode table
#pragma unroll
        for (int r = 0; r < 8; r++) {
            int kk = kgrp * 8 + r;
            int2 dv = __ldg(&g_dec[kt + kk]);
            int kd = dv.y >> 20, kh = (dv.y >> 10) & 1023, kw = dv.y & 1023;
            float v = 0.f;
            if ((unsigned)(id0 + kd) < (unsigned)p.D &&
                (unsigned)(ih0 + kh) < (unsigned)p.H &&
                (unsigned)(iw0 + kw) < (unsigned)p.W)
                v = p.x[base + dv.x];
            Bs[kk][ln] = v;
        }
        __syncthreads();
#pragma unroll
        for (int kq = 0; kq < 16; kq++) {
            float4 a  = *reinterpret_cast<const float4*>(&As[kq][ty * 4]);
            float4 b0 = *reinterpret_cast<const float4*>(&Bs[kq][tx * 4]);
            float4 b1 = *reinterpret_cast<const float4*>(&Bs[kq][64 + tx * 4]);
            float av[4] = {a.x, a.y, a.z, a.w};
            float bv[8] = {b0.x, b0.y, b0.z, b0.w, b1.x, b1.y, b1.z, b1.w};
#pragma unroll
            for (int i = 0; i < 4; i++)
#pragma unroll
                for (int j = 0; j < 8; j++)
                    acc[i][j] = fmaf(av[i], bv[j], acc[i][j]);
        }
        __syncthreads();
    }

#pragma unroll
    for (int i = 0; i < 4; i++) {
        int m = m_base + ty * 4 + i;
        float bvl = p.bias[m];
        float* orow = p.out + (size_t)m * p.outStrideC + p.outOffset + bn * 128;
        float4 o0, o1;
        o0.x = acc[i][0] + bvl; o0.y = acc[i][1] + bvl;
        o0.z = acc[i][2] + bvl; o0.w = acc[i][3] + bvl;
        o1.x = acc[i][4] + bvl; o1.y = acc[i][5] + bvl;
        o1.z = acc[i][6] + bvl; o1.w = acc[i][7] + bvl;
        if (p.gelu) {
            o0.x = gelu_tanh(o0.x); o0.y = gelu_tanh(o0.y);
            o0.z = gelu_tanh(o0.z); o0.w = gelu_tanh(o0.w);
            o1.x = gelu_tanh(o1.x); o1.y = gelu_tanh(o1.y);
            o1.z = gelu_tanh(o1.z); o1.w = gelu_tanh(o1.w);
        }
        *reinterpret_cast<float4*>(orow + tx * 4) = o0;
        *reinterpret_cast<float4*>(orow + 64 + tx * 4) = o1;
    }
}

// ---------------------------------------------------------------------------
// Token GEMM, 64(T) x 128(J) tile. K multiple of 16.
//   ALAYOUT 0: A k-major [K x T];  1: A t-major [T x K] (K mult of 4)
//   OUTMODE 0: C token-major [T x J] = v + bias
//   OUTMODE 1: C channel-major [J x T] += v + bias (residual)
// ---------------------------------------------------------------------------
template <int ALAYOUT, int OUTMODE>
__global__ __launch_bounds__(256) void tok_gemm_kernel(
    const float* __restrict__ A, const float* __restrict__ B,
    const float* __restrict__ bias, float* __restrict__ C,
    int T, int J, int K) {
    __shared__ __align__(16) float As[16][64];
    __shared__ __align__(16) float Bs[16][128];

    const int tid = threadIdx.x;
    const int bj = blockIdx.x, bt = blockIdx.y;
    const int tx = tid & 15, ty = tid >> 4;
    const int lj = tid & 127, kgrp2 = tid >> 7;

    float acc[4][8];
#pragma unroll
    for (int i = 0; i < 4; i++)
#pragma unroll
        for (int j = 0; j < 8; j++) acc[i][j] = 0.f;

    for (int kt = 0; kt < K; kt += 16) {
        if (ALAYOUT == 0) {
            const int lt = tid & 63, kg = tid >> 6;
#pragma unroll
            for (int r = 0; r < 4; r++) {
                int kk = kg * 4 + r;
                As[kk][lt] = A[(size_t)(kt + kk) * T + bt * 64 + lt];
            }
        } else {
            const int lt = tid >> 2, lk4 = (tid & 3) << 2;
            float4 v = *reinterpret_cast<const float4*>(
                A + (size_t)(bt * 64 + lt) * K + kt + lk4);
            As[lk4 + 0][lt] = v.x; As[lk4 + 1][lt] = v.y;
            As[lk4 + 2][lt] = v.z; As[lk4 + 3][lt] = v.w;
        }
#pragma unroll
        for (int r = 0; r < 8; r++) {
            int kk = kgrp2 * 8 + r;
            Bs[kk][lj] = B[(size_t)(kt + kk) * J + bj * 128 + lj];
        }
        __syncthreads();
#pragma unroll
        for (int kq = 0; kq < 16; kq++) {
            float4 a  = *reinterpret_cast<const float4*>(&As[kq][ty * 4]);
            float4 b0 = *reinterpret_cast<const float4*>(&Bs[kq][tx * 4]);
            float4 b1 = *reinterpret_cast<const float4*>(&Bs[kq][64 + tx * 4]);
            float av[4] = {a.x, a.y, a.z, a.w};
            float bv[8] = {b0.x, b0.y, b0.z, b0.w, b1.x, b1.y, b1.z, b1.w};
#pragma unroll
            for (int i = 0; i < 4; i++)
#pragma unroll
                for (int j = 0; j < 8; j++)
                    acc[i][j] = fmaf(av[i], bv[j], acc[i][j]);
        }
        __syncthreads();
    }

    if (OUTMODE == 0) {
#pragma unroll
        for (int i = 0; i < 4; i++) {
            int t = bt * 64 + ty * 4 + i;
            int j0 = bj * 128 + tx * 4;
            int j1 = j0 + 64;
            float4 o0, o1;
            o0.x = acc[i][0] + bias[j0 + 0]; o0.y = acc[i][1] + bias[j0 + 1];
            o0.z = acc[i][2] + bias[j0 + 2]; o0.w = acc[i][3] + bias[j0 + 3];
            o1.x = acc[i][4] + bias[j1 + 0]; o1.y = acc[i][5] + bias[j1 + 1];
            o1.z = acc[i][6] + bias[j1 + 2]; o1.w = acc[i][7] + bias[j1 + 3];
            *reinterpret_cast<float4*>(C + (size_t)t * J + j0) = o0;
            *reinterpret_cast<float4*>(C + (size_t)t * J + j1) = o1;
        }
    } else {
        int t0 = bt * 64 + ty * 4;
#pragma unroll
        for (int j = 0; j < 4; j++) {
            int jj = bj * 128 + tx * 4 + j;
            float bvl = bias[jj];
            float4* cp = reinterpret_cast<float4*>(C + (size_t)jj * T + t0);
            float4 o = *cp;
            o.x += acc[0][j] + bvl; o.y += acc[1][j] + bvl;
            o.z += acc[2][j] + bvl; o.w += acc[3][j] + bvl;
            *cp = o;
        }
#pragma unroll
        for (int j = 0; j < 4; j++) {
            int jj = bj * 128 + 64 + tx * 4 + j;
            float bvl = bias[jj];
            float4* cp = reinterpret_cast<float4*>(C + (size_t)jj * T + t0);
            float4 o = *cp;
            o.x += acc[0][4 + j] + bvl; o.y += acc[1][4 + j] + bvl;
            o.z += acc[2][4 + j] + bvl; o.w += acc[3][4 + j] + bvl;
            *cp = o;
        }
    }
}

// ---------------------------------------------------------------------------
// LayerNorm over C=512, channel-major in/out.
// ---------------------------------------------------------------------------
__global__ __launch_bounds__(256) void layernorm_kernel(
    const float* __restrict__ x, const float* __restrict__ g,
    const float* __restrict__ b, float* __restrict__ y, int T) {
    const int tx = threadIdx.x;
    const int ty = threadIdx.y;
    const int t = blockIdx.x * 32 + tx;

    float s = 0.f, ss = 0.f;
#pragma unroll
    for (int i = 0; i < 64; i++) {
        int c = ty * 64 + i;
        float v = x[(size_t)c * T + t];
        s += v; ss += v * v;
    }
    __shared__ float shs[8][32], shss[8][32];
    __shared__ float smu[32], srs[32];
    shs[ty][tx] = s; shss[ty][tx] = ss;
    __syncthreads();
    if (ty == 0) {
        float S = 0.f, SS = 0.f;
#pragma unroll
        for (int j = 0; j < 8; j++) { S += shs[j][tx]; SS += shss[j][tx]; }
        float mu = S * (1.f / 512.f);
        float var = SS * (1.f / 512.f) - mu * mu;
        smu[tx] = mu;
        srs[tx] = rsqrtf(var + 1e-5f);
    }
    __syncthreads();
    float mu = smu[tx], rs = srs[tx];
#pragma unroll
    for (int i = 0; i < 64; i++) {
        int c = ty * 64 + i;
        float v = x[(size_t)c * T + t];
        y[(size_t)c * T + t] = (v - mu) * rs * g[c] + b[c];
    }
}

// ---------------------------------------------------------------------------
// Neighborhood attention, one warp per (token, head), table-driven offsets.
// ---------------------------------------------------------------------------
__global__ __launch_bounds__(256) void natt_kernel(
    const float* __restrict__ qkv, float* __restrict__ at) {
    const int warp = threadIdx.x >> 5;
    const int lane = threadIdx.x & 31;
    const int t = blockIdx.x * 8 + warp;
    const int head = blockIdx.y;
    const int d = t >> 11;
    const int hh = (t >> 6) & 31;
    const int ww = t & 63;

    __shared__ float qsh[8][64];
    __shared__ float psh[8][248];
    const float* qp = qkv + (size_t)t * 1536 + head * 64;
    qsh[warp][lane] = qp[lane] * 0.125f;
    qsh[warp][lane + 32] = qp[lane + 32] * 0.125f;
    __syncwarp();

    float sc[8];
    float m = -1e30f;
#pragma unroll
    for (int it = 0; it < 8; it++) {
        int nb = it * 32 + lane;
        float dot = -1e30f;
        if (nb < 245) {
            int pk = g_npack[nb];
            int nd = d + (pk >> 16) - 2;
            int nh = hh + ((pk >> 8) & 255) - 3;
            int nw = ww + (pk & 255) - 3;
            if ((unsigned)nd < 4u && (unsigned)nh < 32u && (unsigned)nw < 64u) {
                int nt = t + g_ndelta[nb];
                const float4* kp = reinterpret_cast<const float4*>(
                    qkv + (size_t)nt * 1536 + 512 + head * 64);
                float s = 0.f;
#pragma unroll
                for (int q4 = 0; q4 < 16; q4++) {
                    float4 kv = kp[q4];
                    s = fmaf(qsh[warp][q4 * 4 + 0], kv.x, s);
                    s = fmaf(qsh[warp][q4 * 4 + 1], kv.y, s);
                    s = fmaf(qsh[warp][q4 * 4 + 2], kv.z, s);
                    s = fmaf(qsh[warp][q4 * 4 + 3], kv.w, s);
                }
                dot = s;
            }
        }
        sc[it] = dot;
        m = fmaxf(m, dot);
    }
#pragma unroll
    for (int o = 16; o; o >>= 1) m = fmaxf(m, __shfl_xor_sync(0xffffffffu, m, o));

    float l = 0.f;
#pragma unroll
    for (int it = 0; it < 8; it++) {
        int nb = it * 32 + lane;
        float e = (sc[it] > -1e29f) ? __expf(sc[it] - m) : 0.f;
        if (nb < 248) psh[warp][nb] = e;
        l += e;
    }
#pragma unroll
    for (int o = 16; o; o >>= 1) l += __shfl_xor_sync(0xffffffffu, l, o);
    __syncwarp();

    float acc0 = 0.f, acc1 = 0.f;
    for (int nb = 0; nb < 245; nb++) {
        float pb = psh[warp][nb];
        if (pb > 0.f) {
            int nt = t + g_ndelta[nb];
            const float* vp = qkv + (size_t)nt * 1536 + 1024 + head * 64;
            acc0 = fmaf(pb, vp[lane], acc0);
            acc1 = fmaf(pb, vp[lane + 32], acc1);
        }
    }
    float inv = 1.f / l;
    float* op = at + (size_t)t * 512 + head * 64;
    op[lane] = acc0 * inv;
    op[lane + 32] = acc1 * inv;
}

// ---------------------------------------------------------------------------
// Host launcher
// ---------------------------------------------------------------------------
static inline int kpad16(int k) { return (k + 15) & ~15; }

extern "C" void kernel_launch(void* const* d_in, const int* in_sizes, int n_in,
                              void* d_out, int out_size) {
    const float* x2d  = (const float*)d_in[0];
    const float* x3d  = (const float*)d_in[1];
    const float* sw0  = (const float*)d_in[2];  const float* sb0 = (const float*)d_in[3];
    const float* sw1  = (const float*)d_in[4];  const float* sb1 = (const float*)d_in[5];
    const float* sw2  = (const float*)d_in[6];  const float* sb2 = (const float*)d_in[7];
    const float* pw0  = (const float*)d_in[8];  const float* pb0 = (const float*)d_in[9];
    const float* pw1  = (const float*)d_in[10]; const float* pb1 = (const float*)d_in[11];
    const float* pw2  = (const float*)d_in[12]; const float* pb2 = (const float*)d_in[13];
    const float* latw = (const float*)d_in[14]; const float* latb = (const float*)d_in[15];
    const float* lng  = (const float*)d_in[16]; const float* lnb  = (const float*)d_in[17];
    const float* qkvw = (const float*)d_in[18]; const float* qkvb = (const float*)d_in[19];
    const float* pjw  = (const float*)d_in[20]; const float* pjb  = (const float*)d_in[21];
    float* lat = (float*)d_out;

    float *s0, *s1, *p0, *p1, *feats, *yn, *qkvB, *at;
    cudaGetSymbolAddress((void**)&s0, g_s0);
    cudaGetSymbolAddress((void**)&s1, g_s1);
    cudaGetSymbolAddress((void**)&p0, g_p0);
    cudaGetSymbolAddress((void**)&p1, g_p1);
    cudaGetSymbolAddress((void**)&feats, g_feats);
    cudaGetSymbolAddress((void**)&yn, g_yn);
    cudaGetSymbolAddress((void**)&qkvB, g_qkv);
    cudaGetSymbolAddress((void**)&at, g_at);

    natt_table_kernel<<<1, 256>>>();

    // ---- 2D conv tower ----
    {
        int K = 72, Kp = kpad16(K);
        conv_decode_kernel<<<(Kp + 255) / 256, 256>>>(K, Kp, 9, 9, 3, 1, 256, 512);
        ConvParams p{ x2d, sw0, sb0, s0, 1, 256, 512, 128, 256,
                      1, 2, 2, 0, 1, 1, K, Kp, 32768, 0, 1 };
        conv_gemm_kernel<<<dim3(32768 / 128, 128 / 64), 256>>>(p);
    }
    {
        int K = 1152, Kp = kpad16(K);
        conv_decode_kernel<<<(Kp + 255) / 256, 256>>>(K, Kp, 9, 9, 3, 1, 128, 256);
        ConvParams p{ s0, sw1, sb1, s1, 1, 128, 256, 64, 128,
                      1, 2, 2, 0, 1, 1, K, Kp, 8192, 0, 1 };
        conv_gemm_kernel<<<dim3(8192 / 128, 256 / 64), 256>>>(p);
    }
    {
        int K = 2304, Kp = kpad16(K);
        conv_decode_kernel<<<(Kp + 255) / 256, 256>>>(K, Kp, 9, 9, 3, 1, 64, 128);
        ConvParams p{ s1, sw2, sb2, feats, 1, 64, 128, 32, 64,
                      1, 2, 2, 0, 1, 1, K, Kp, 8192, 3 * 2048, 1 };
        conv_gemm_kernel<<<dim3(2048 / 128, 512 / 64), 256>>>(p);
    }

    // ---- 3D conv tower ----
    {
        int K = 135, Kp = kpad16(K);
        conv_decode_kernel<<<(Kp + 255) / 256, 256>>>(K, Kp, 27, 9, 3, 24, 256, 512);
        ConvParams p{ x3d, pw0, pb0, p0, 24, 256, 512, 128, 256,
                      2, 2, 2, 1, 1, 1, K, Kp, 393216, 0, 1 };
        conv_gemm_kernel<<<dim3(393216 / 128, 128 / 64), 256>>>(p);
    }
    {
        int K = 3456, Kp = kpad16(K);
        conv_decode_kernel<<<(Kp + 255) / 256, 256>>>(K, Kp, 27, 9, 3, 12, 128, 256);
        ConvParams p{ p0, pw1, pb1, p1, 12, 128, 256, 64, 128,
                      2, 2, 2, 1, 1, 1, K, Kp, 49152, 0, 1 };
        conv_gemm_kernel<<<dim3(49152 / 128, 256 / 64), 256>>>(p);
    }
    {
        int K = 6912, Kp = kpad16(K);
        conv_decode_kernel<<<(Kp + 255) / 256, 256>>>(K, Kp, 27, 9, 3, 6, 64, 128);
        ConvParams p{ p1, pw2, pb2, feats, 6, 64, 128, 32, 64,
                      2, 2, 2, 1, 1, 1, K, Kp, 8192, 0, 1 };
        conv_gemm_kernel<<<dim3(6144 / 128, 512 / 64), 256>>>(p);
    }

    // ---- lateral 1x1x1 conv -> d_out ----
    {
        int K = 512, Kp = 512;
        conv_decode_kernel<<<(Kp + 255) / 256, 256>>>(K, Kp, 1, 1, 1, 4, 32, 64);
        ConvParams p{ feats, latw, latb, lat, 4, 32, 64, 32, 64,
                      1, 1, 1, 0, 0, 0, K, Kp, 8192, 0, 0 };
        conv_gemm_kernel<<<dim3(8192 / 128, 512 / 64), 256>>>(p);
    }

    // ---- 3 neighborhood-attention blocks ----
    for (int i = 0; i < 3; i++) {
        layernorm_kernel<<<8192 / 32, dim3(32, 8)>>>(lat, lng + i * 512, lnb + i * 512,
                                                     yn, 8192);
        tok_gemm_kernel<0, 0><<<dim3(1536 / 128, 8192 / 64), 256>>>(
            yn, qkvw + (size_t)i * 512 * 1536, qkvb + i * 1536, qkvB, 8192, 1536, 512);
        natt_kernel<<<dim3(8192 / 8, 8), 256>>>(qkvB, at);
        tok_gemm_kernel<1, 1><<<dim3(512 / 128, 8192 / 64), 256>>>(
            at, pjw + (size_t)i * 512 * 512, pjb + i * 512, lat, 8192, 512, 512);
    }
}